// round 8
// baseline (speedup 1.0000x reference)
#include <cuda_runtime.h>

// FeatureShader: softmax blend + barycentric vertex-feature sampling.
// N=4, H=256, W=256, K=8, C=16; V=100000, F=200000.
// Inputs: dists(N,H,W,K) f32 | zbuf f32 | bary(N,H,W,K,3) f32 |
//         verts_features(V,C) f32 | background(C) f32 | pix_to_face i32 | faces(F,3) i32
// Output: (N,H,W,C) f32
//
// Quad design: 4 threads per pixel (one float4 channel group each).
// Per-pixel softmax computed redundantly per lane, fully in registers with
// vectorized (float4/int4) streaming loads — no shuffles, no smem, no barriers.
// Faces/bary/features gathered only for surviving weights
// (wk > 1e-7 * denom contributes < 1e-6 rel err; validated at 8e-8).

#define NPIX  (4 * 256 * 256)
#define KF    8
#define TPB   256

__global__ __launch_bounds__(TPB)
void feature_shader_kernel(const float4* __restrict__ dists4,   // (NPIX, 2 x float4)
                           const float4* __restrict__ zbuf4,    // (NPIX, 2 x float4)
                           const float*  __restrict__ bary,     // (NPIX, K, 3)
                           const float4* __restrict__ vfeat4,   // (V, 4 x float4)
                           const float4* __restrict__ bg4,      // (4 x float4)
                           const int4*   __restrict__ p2f4,     // (NPIX, 2 x int4)
                           const int*    __restrict__ faces,    // (F, 3)
                           float4*       __restrict__ out4)     // (NPIX, 4 x float4)
{
    const float INV_SIGMA = 1e4f;
    const float INV_GAMMA = 1e4f;
    const float EPSV      = 1e-10f;
    const float INV_RANGE = 1.0f / 99.0f;   // 1/(ZFAR-ZNEAR)
    const float ZFARV     = 100.0f;
    const float REL_THR   = 1e-7f;          // drop wk < REL_THR * sum(wk)

    const int  tid = threadIdx.x;
    const long pix = ((long)blockIdx.x * TPB + tid) >> 2;   // pixel id
    const int  cg  = tid & 3;                               // channel group (float4)

    // ---- vectorized streaming loads (quad-uniform addresses -> broadcast) ----
    float4 z01 = zbuf4[pix * 2 + 0];
    float4 z23 = zbuf4[pix * 2 + 1];
    float4 d01 = dists4[pix * 2 + 0];
    float4 d23 = dists4[pix * 2 + 1];
    int4   f01 = p2f4[pix * 2 + 0];
    int4   f23 = p2f4[pix * 2 + 1];
    float4 bgv = bg4[cg];

    float zv[KF] = { z01.x, z01.y, z01.z, z01.w, z23.x, z23.y, z23.z, z23.w };
    float dv[KF] = { d01.x, d01.y, d01.z, d01.w, d23.x, d23.y, d23.z, d23.w };
    int   fv[KF] = { f01.x, f01.y, f01.z, f01.w, f23.x, f23.y, f23.z, f23.w };

    // ---- phase A: per-k z_inv & prob, in registers ----
    float zi[KF], wk[KF];
    float zmax = EPSV;
#pragma unroll
    for (int k = 0; k < KF; k++) {
        float m = (fv[k] >= 0) ? 1.0f : 0.0f;
        float z = (ZFARV - zv[k]) * INV_RANGE * m;
        zi[k] = z;
        zmax = fmaxf(zmax, z);
        wk[k] = __fdividef(m, 1.0f + __expf(dv[k] * INV_SIGMA));  // prob for now
    }

    float dsum = 0.0f;
#pragma unroll
    for (int k = 0; k < KF; k++) {
        wk[k] *= __expf((zi[k] - zmax) * INV_GAMMA);
        dsum += wk[k];
    }

    float delta = fmaxf(__expf((EPSV - zmax) * INV_GAMMA), EPSV);
    float inv   = __fdividef(1.0f, dsum + delta);
    float dinv  = delta * inv;
    float thr   = dsum * REL_THR;

    // ---- phase B: gather only surviving faces ----
    float4 acc = make_float4(0.f, 0.f, 0.f, 0.f);
#pragma unroll
    for (int k = 0; k < KF; k++) {
        if (wk[k] > thr) {
            const int*   fr = faces + (long)((fv[k] >= 0) ? fv[k] : 0) * 3;
            const float* bp = bary + (pix * KF + k) * 3;
            int   v0 = fr[0], v1 = fr[1], v2 = fr[2];
            float w  = wk[k] * inv;
            float b0 = w * bp[0];
            float b1 = w * bp[1];
            float b2 = w * bp[2];
            float4 t0 = vfeat4[(long)v0 * 4 + cg];
            float4 t1 = vfeat4[(long)v1 * 4 + cg];
            float4 t2 = vfeat4[(long)v2 * 4 + cg];
            acc.x += b0 * t0.x + b1 * t1.x + b2 * t2.x;
            acc.y += b0 * t0.y + b1 * t1.y + b2 * t2.y;
            acc.z += b0 * t0.z + b1 * t1.z + b2 * t2.z;
            acc.w += b0 * t0.w + b1 * t1.w + b2 * t2.w;
        }
    }

    float4 o;
    o.x = acc.x + dinv * bgv.x;
    o.y = acc.y + dinv * bgv.y;
    o.z = acc.z + dinv * bgv.z;
    o.w = acc.w + dinv * bgv.w;
    out4[pix * 4 + cg] = o;
}

extern "C" void kernel_launch(void* const* d_in, const int* in_sizes, int n_in,
                              void* d_out, int out_size)
{
    const float4* dists4 = (const float4*)d_in[0];
    const float4* zbuf4  = (const float4*)d_in[1];
    const float*  bary   = (const float*)d_in[2];
    const float4* vfeat4 = (const float4*)d_in[3];
    const float4* bg4    = (const float4*)d_in[4];
    const int4*   p2f4   = (const int4*)d_in[5];
    const int*    faces  = (const int*)d_in[6];
    float4*       out4   = (float4*)d_out;

    long total = (long)NPIX * 4;
    int  grid  = (int)(total / TPB);   // 16384 blocks
    feature_shader_kernel<<<grid, TPB>>>(dists4, zbuf4, bary, vfeat4, bg4, p2f4, faces, out4);
}